// round 10
// baseline (speedup 1.0000x reference)
#include <cuda_runtime.h>
#include <cstdint>
#include <math.h>

#define SX 18
#define KS 13
#define W4 28561
#define W3 2197
#define W2 169
#define X3 5832
#define X2 324
#define XB 104976

#define APITCH 24
#define AROWS  656
#define BPITCH 28
#define AWORDS (AROWS * APITCH)               // 15744 words
#define BWORDS (13 * 24 * BPITCH)             // 9828 words
#define TOTWORDS (2 * AWORDS + 2 * BWORDS)    // 51144
#define SMEM_BYTES (TOTWORDS * 4)             // 204576 B
#define ABYTES (AWORDS * 4)
#define BBASE  (2 * AWORDS)
#define NT 512

__device__ __forceinline__ uint32_t tf32r(float f) {
    uint32_t r; asm("cvt.rna.tf32.f32 %0, %1;" : "=r"(r) : "f"(f)); return r;
}
__device__ __forceinline__ uint32_t smem_u32(const void* p) {
    uint32_t a; asm("{ .reg .u64 t; cvta.to.shared.u64 t, %1; cvt.u32.u64 %0, t; }"
                    : "=r"(a) : "l"(p));
    return a;
}
__device__ __forceinline__ void cp8(uint32_t dst, const void* src) {
    asm volatile("cp.async.ca.shared.global [%0], [%1], 8;"
                 :: "r"(dst), "l"(src) : "memory");
}

// a0=A[g][k0], a1=A[g+8][k0], a2=A[g][k1], a3=A[g+8][k1]; k0=2tig,k1=2tig+1
// mirrored in B rows (consistent k-permutation).
__device__ __forceinline__ void mma8(float* c, uint2 alo, uint2 ahi,
                                     const uint32_t* b) {
    asm volatile(
        "mma.sync.aligned.m16n8k8.row.col.f32.tf32.tf32.f32 "
        "{%0,%1,%2,%3}, {%4,%5,%6,%7}, {%8,%9}, {%0,%1,%2,%3};"
        : "+f"(c[0]), "+f"(c[1]), "+f"(c[2]), "+f"(c[3])
        : "r"(alo.x), "r"(ahi.x), "r"(alo.y), "r"(ahi.y),
          "r"(b[0]), "r"(b[1]));
}

__global__ __launch_bounds__(NT, 1)
void conv4d_mma_w16(const float* __restrict__ x,  const float* __restrict__ cw,
                    const float* __restrict__ cb, const float* __restrict__ lw,
                    const float* __restrict__ lb, float* __restrict__ out)
{
    extern __shared__ uint32_t smem[];
    const uint32_t sbase = smem_u32(smem);

    const int b   = blockIdx.x;
    const int tid = threadIdx.x;
    const int wid = tid >> 5;
    const int lid = tid & 31;
    const int g   = lid >> 2;
    const int tig = lid & 3;

    // warp = (m-quarter, kx-group)
    const int mq  = wid & 3;                        // tiles: 4/4/3/3
    const int kg  = wid >> 2;                       // kx:    4/3/3/3
    const int tbase  = (mq < 2) ? 4 * mq : 8 + 3 * (mq - 2);
    const int tcount = (mq < 2) ? 4 : 3;
    const int kxs = (kg == 0) ? 0 : 1 + 3 * kg;     // 0,4,7,10
    const int kxe = kxs + ((kg == 0) ? 4 : 3);

    // C frags: up to 4 m-tiles x 3 n-tiles x 4
    float c[4][3][4];
    #pragma unroll
    for (int t = 0; t < 4; ++t)
        #pragma unroll
        for (int n = 0; n < 3; ++n)
            #pragma unroll
            for (int v = 0; v < 4; ++v) c[t][n][v] = 0.f;

    // per-thread A staging offsets (12 float2 copies max)
    int      srcb[12];
    uint32_t dstb[12];
    #pragma unroll
    for (int k = 0; k < 12; ++k) {
        int u = tid + k * NT;
        if (u < 5832) {
            int row = u / 9;   int j   = u - row * 9;
            int ix  = row / 36; int oyz = row - ix * 36;
            int oy  = oyz / 6;  int oz  = oyz - oy * 6;
            srcb[k] = (ix * X3 + oy * X2 + oz * SX + 2 * j) * 4;
            dstb[k] = sbase + (uint32_t)(row * APITCH + 2 * j) * 4;
        } else srcb[k] = -1;
    }

    for (int i = tid; i < TOTWORDS; i += NT) smem[i] = 0u;
    __syncthreads();

    const float* xb = x + (size_t)b * XB;
    const char*  xc = (const char*)xb;

    // ---- prologue: stage iteration 0 into buffer 0 ----
    {
        #pragma unroll
        for (int k = 0; k < 12; ++k)
            if (srcb[k] >= 0) cp8(dstb[k], xc + srcb[k]);
        asm volatile("cp.async.commit_group;" ::: "memory");
        if (tid < 507) {
            int t = tid;
            int kx = t / 39; int r = t - kx * 39;
            int ch = r / 13; int kw = r - ch * 13;
            uint32_t val = tf32r(cw[ch * W4 + kx * W3 + kw]);   // ky=kz=0
            uint32_t* dst = smem + BBASE + kx * (24 * BPITCH) + ch * 6;
            #pragma unroll
            for (int ow = 0; ow < 6; ++ow)
                dst[(kw + ow) * BPITCH + ow] = val;
        }
    }

    #pragma unroll 1
    for (int i = 0; i < 169; ++i) {
        asm volatile("cp.async.wait_group 0;" ::: "memory");
        __syncthreads();

        if (i < 168) {
            const int ni = i + 1;
            const int ky = ni / 13, kz = ni - 13 * (ni / 13);
            const int d  = (ky * X2 + kz * SX) * 4;
            const uint32_t ab = (uint32_t)((ni & 1) * ABYTES);
            #pragma unroll
            for (int k = 0; k < 12; ++k)
                if (srcb[k] >= 0) cp8(dstb[k] + ab, xc + srcb[k] + d);
            asm volatile("cp.async.commit_group;" ::: "memory");

            if (tid < 507) {
                int t = tid;
                int kx = t / 39; int r = t - kx * 39;
                int ch = r / 13; int kw = r - ch * 13;
                uint32_t val = tf32r(cw[ch * W4 + kx * W3 + ky * W2 + kz * KS + kw]);
                uint32_t* dst = smem + BBASE + (ni & 1) * BWORDS
                              + kx * (24 * BPITCH) + ch * 6;
                #pragma unroll
                for (int ow = 0; ow < 6; ++ow)
                    dst[(kw + ow) * BPITCH + ow] = val;
            }
        }

        // ---- compute(i): own kx-group x own m-tiles ----
        const uint32_t* slab = smem + (i & 1) * AWORDS;
        const uint32_t* Bs   = smem + BBASE + (i & 1) * BWORDS;
        #pragma unroll 1
        for (int kx = kxs; kx < kxe; ++kx) {
            uint32_t bf[3][3][2];
            const uint32_t* Bk = Bs + kx * (24 * BPITCH) + (2 * tig) * BPITCH + g;
            #pragma unroll
            for (int ks = 0; ks < 3; ++ks)
                #pragma unroll
                for (int nt = 0; nt < 3; ++nt) {
                    bf[ks][nt][0] = Bk[ks * 8 * BPITCH + nt * 8];
                    bf[ks][nt][1] = Bk[ks * 8 * BPITCH + BPITCH + nt * 8];
                }
            #pragma unroll
            for (int t = 0; t < 4; ++t) {
                if (t < tcount) {
                    const uint32_t* Ar = slab
                        + ((tbase + t) * 16 + g + 36 * kx) * APITCH + 2 * tig;
                    uint2 alo[3], ahi[3];
                    #pragma unroll
                    for (int ks = 0; ks < 3; ++ks) {
                        alo[ks] = *(const uint2*)(Ar + ks * 8);
                        ahi[ks] = *(const uint2*)(Ar + 8 * APITCH + ks * 8);
                    }
                    #pragma unroll
                    for (int ks = 0; ks < 3; ++ks)
                        #pragma unroll
                        for (int nt = 0; nt < 3; ++nt)
                            mma8(c[t][nt], alo[ks], ahi[ks], bf[ks][nt]);
                }
            }
        }
    }

    // ---- reduce C across the 4 kx-groups (tile-indexed, 4 phases) ----
    __syncthreads();
    float* Cred = (float*)smem;            // 5376 floats
    #pragma unroll 1
    for (int ph = 0; ph < 4; ++ph) {
        if (kg == ph) {
            #pragma unroll
            for (int t = 0; t < 4; ++t)
                if (t < tcount) {
                    int tile = tbase + t;
                    #pragma unroll
                    for (int nt = 0; nt < 3; ++nt)
                        #pragma unroll
                        for (int v = 0; v < 4; ++v) {
                            int idx = ((tile * 3 + nt) * 4 + v) * 32 + lid;
                            if (ph == 0) Cred[idx] = c[t][nt][v];
                            else         Cred[idx] += c[t][nt][v];
                        }
                }
        }
        __syncthreads();
    }

    // ---- epilogue: bias + ReLU + dot(lin_w) over 5376 C elements ----
    float partial = 0.f;
    #pragma unroll 1
    for (int e = tid; e < 5376; e += NT) {
        int ln = e & 31;  int q  = e >> 5;
        int v  = q & 3;   int q2 = q >> 2;
        int nt = q2 % 3;  int tile = q2 / 3;
        int m = tile * 16 + (ln >> 2) + (v >> 1) * 8;
        int n = nt * 8 + (ln & 3) * 2 + (v & 1);
        if (m < 216 && n < 18) {
            int ox = m / 36; int oyz = m - ox * 36;
            int ch = n / 6;  int ow  = n - ch * 6;
            float h = Cred[e] + __ldg(cb + ch);
            h = fmaxf(h, 0.f);
            partial = fmaf(h, __ldg(lw + ch * 1296 + ox * 216 + oyz * 6 + ow),
                           partial);
        }
    }

    float* red = (float*)smem + 8192;
    red[tid] = partial;
    __syncthreads();
    if (tid < 256) red[tid] += red[tid + 256];
    __syncthreads();
    if (tid < 128) red[tid] += red[tid + 128];
    __syncthreads();
    if (tid < 64)  red[tid] += red[tid + 64];
    __syncthreads();
    if (tid < 32) {
        float v = red[tid] + red[tid + 32];
        #pragma unroll
        for (int off = 16; off > 0; off >>= 1)
            v += __shfl_down_sync(0xffffffffu, v, off);
        if (tid == 0) {
            float z = v + __ldg(lb);
            out[b] = 1.f / (1.f + expf(-z));
        }
    }
}

extern "C" void kernel_launch(void* const* d_in, const int* in_sizes, int n_in,
                              void* d_out, int out_size)
{
    const float* x      = (const float*)d_in[0];
    const float* conv_w = (const float*)d_in[1];
    const float* conv_b = (const float*)d_in[2];
    const float* lin_w  = (const float*)d_in[3];
    const float* lin_b  = (const float*)d_in[4];
    float* out = (float*)d_out;

    cudaFuncSetAttribute(conv4d_mma_w16,
                         cudaFuncAttributeMaxDynamicSharedMemorySize, SMEM_BYTES);
    conv4d_mma_w16<<<512, NT, SMEM_BYTES>>>(x, conv_w, conv_b, lin_w, lin_b, out);
}

// round 12
// speedup vs baseline: 1.0623x; 1.0623x over previous
#include <cuda_runtime.h>
#include <cstdint>
#include <math.h>

#define SX 18
#define KS 13
#define W4 28561
#define W3 2197
#define W2 169
#define X3 5832
#define X2 324
#define XB 104976

#define APITCH 24
#define AROWS  656
#define BPITCH 28
#define AWORDS (AROWS * APITCH)               // 15744 words
#define BWORDS (13 * 24 * BPITCH)             // 9828 words
#define TOTWORDS (AWORDS + BWORDS)            // 25572
#define SMEM_BYTES (TOTWORDS * 4)             // 102288 B -> 2 blocks/SM
#define NT 256

__device__ __forceinline__ uint32_t tf32r(float f) {
    uint32_t r; asm("cvt.rna.tf32.f32 %0, %1;" : "=r"(r) : "f"(f)); return r;
}
__device__ __forceinline__ uint32_t smem_u32(const void* p) {
    uint32_t a; asm("{ .reg .u64 t; cvta.to.shared.u64 t, %1; cvt.u32.u64 %0, t; }"
                    : "=r"(a) : "l"(p));
    return a;
}
__device__ __forceinline__ void cp8(uint32_t dst, const void* src) {
    asm volatile("cp.async.ca.shared.global [%0], [%1], 8;"
                 :: "r"(dst), "l"(src) : "memory");
}

// a0=A[g][k0], a1=A[g+8][k0], a2=A[g][k1], a3=A[g+8][k1]; k0=2tig,k1=2tig+1
// mirrored in B rows (consistent k-permutation).
__device__ __forceinline__ void mma8(float* c, uint2 alo, uint2 ahi,
                                     const uint32_t* b) {
    asm volatile(
        "mma.sync.aligned.m16n8k8.row.col.f32.tf32.tf32.f32 "
        "{%0,%1,%2,%3}, {%4,%5,%6,%7}, {%8,%9}, {%0,%1,%2,%3};"
        : "+f"(c[0]), "+f"(c[1]), "+f"(c[2]), "+f"(c[3])
        : "r"(alo.x), "r"(ahi.x), "r"(alo.y), "r"(ahi.y),
          "r"(b[0]), "r"(b[1]));
}

__global__ __launch_bounds__(NT, 2)
void conv4d_mma_pair(const float* __restrict__ x,  const float* __restrict__ cw,
                     const float* __restrict__ cb, const float* __restrict__ lw,
                     const float* __restrict__ lb, float* __restrict__ out)
{
    extern __shared__ uint32_t smem[];
    const uint32_t sbase = smem_u32(smem);

    const int b   = blockIdx.x;
    const int tid = threadIdx.x;
    const int wid = tid >> 5;
    const int lid = tid & 31;
    const int g   = lid >> 2;
    const int tig = lid & 3;

    // warp = (m-quarter, kx-half)
    const int mq  = wid & 3;                        // tiles: 4/4/3/3
    const int kg  = wid >> 2;                       // kx: 7/6
    const int tbase  = (mq < 2) ? 4 * mq : 8 + 3 * (mq - 2);
    const int tcount = (mq < 2) ? 4 : 3;
    const int kxs = (kg == 0) ? 0 : 7;
    const int kxe = (kg == 0) ? 7 : 13;

    float c[4][3][4];
    #pragma unroll
    for (int t = 0; t < 4; ++t)
        #pragma unroll
        for (int n = 0; n < 3; ++n)
            #pragma unroll
            for (int v = 0; v < 4; ++v) c[t][n][v] = 0.f;

    // per-thread A staging offsets, packed: (src float2-idx << 13) | dst float2-idx
    uint32_t pk[23];
    #pragma unroll
    for (int k = 0; k < 23; ++k) {
        int u = tid + k * NT;
        if (u < 5832) {
            int row = u / 9;   int j   = u - row * 9;
            int ix  = row / 36; int oyz = row - ix * 36;
            int oy  = oyz / 6;  int oz  = oyz - oy * 6;
            uint32_t srcU = (uint32_t)((ix * X3 + oy * X2 + oz * SX + 2 * j) >> 1);
            uint32_t dstU = (uint32_t)(row * 12 + j);
            pk[k] = (srcU << 13) | dstU;
        } else pk[k] = 0xFFFFFFFFu;
    }

    for (int i = tid; i < TOTWORDS; i += NT) smem[i] = 0u;

    const float* xb = x + (size_t)b * XB;
    const char*  xc = (const char*)xb;
    uint32_t* Bs = smem + AWORDS;

    #pragma unroll 1
    for (int i = 0; i < 169; ++i) {
        const int ky = i / 13, kz = i - 13 * (i / 13);
        const int d  = (ky * X2 + kz * SX) * 4;

        __syncthreads();   // previous compute's slab/B readers done

        #pragma unroll
        for (int k = 0; k < 23; ++k) {
            uint32_t p = pk[k];
            if (p != 0xFFFFFFFFu)
                cp8(sbase + (p & 8191u) * 8u, xc + (size_t)(p >> 13) * 8 + d);
        }
        asm volatile("cp.async.commit_group;" ::: "memory");

        // FIX (R11 bug): must cover all 507 weights with NT=256 threads
        for (int t = tid; t < 507; t += NT) {
            int kx = t / 39; int r = t - kx * 39;
            int ch = r / 13; int kw = r - ch * 13;
            uint32_t val = tf32r(cw[ch * W4 + kx * W3 + ky * W2 + kz * KS + kw]);
            uint32_t* dst = Bs + kx * (24 * BPITCH) + ch * 6;
            #pragma unroll
            for (int ow = 0; ow < 6; ++ow)
                dst[(kw + ow) * BPITCH + ow] = val;
        }

        asm volatile("cp.async.wait_group 0;" ::: "memory");
        __syncthreads();   // slab + B staged

        // ---- compute(i): own kx-half x own m-quarter ----
        #pragma unroll 1
        for (int kx = kxs; kx < kxe; ++kx) {
            uint32_t bf[3][3][2];
            const uint32_t* Bk = Bs + kx * (24 * BPITCH) + (2 * tig) * BPITCH + g;
            #pragma unroll
            for (int ks = 0; ks < 3; ++ks)
                #pragma unroll
                for (int nt = 0; nt < 3; ++nt) {
                    bf[ks][nt][0] = Bk[ks * 8 * BPITCH + nt * 8];
                    bf[ks][nt][1] = Bk[ks * 8 * BPITCH + BPITCH + nt * 8];
                }
            #pragma unroll
            for (int t = 0; t < 4; ++t) {
                if (t < tcount) {
                    const uint32_t* Ar = smem
                        + ((tbase + t) * 16 + g + 36 * kx) * APITCH + 2 * tig;
                    uint2 alo[3], ahi[3];
                    #pragma unroll
                    for (int ks = 0; ks < 3; ++ks) {
                        alo[ks] = *(const uint2*)(Ar + ks * 8);
                        ahi[ks] = *(const uint2*)(Ar + 8 * APITCH + ks * 8);
                    }
                    #pragma unroll
                    for (int ks = 0; ks < 3; ++ks)
                        #pragma unroll
                        for (int nt = 0; nt < 3; ++nt)
                            mma8(c[t][nt], alo[ks], ahi[ks], bf[ks][nt]);
                }
            }
        }
    }

    // ---- reduce C across the 2 kx-halves (tile-indexed, 2 phases) ----
    __syncthreads();
    float* Cred = (float*)smem;            // 5376 floats
    #pragma unroll 1
    for (int ph = 0; ph < 2; ++ph) {
        if (kg == ph) {
            #pragma unroll
            for (int t = 0; t < 4; ++t)
                if (t < tcount) {
                    int tile = tbase + t;
                    #pragma unroll
                    for (int nt = 0; nt < 3; ++nt)
                        #pragma unroll
                        for (int v = 0; v < 4; ++v) {
                            int idx = ((tile * 3 + nt) * 4 + v) * 32 + lid;
                            if (ph == 0) Cred[idx] = c[t][nt][v];
                            else         Cred[idx] += c[t][nt][v];
                        }
                }
        }
        __syncthreads();
    }

    // ---- epilogue: bias + ReLU + dot(lin_w) over 5376 C elements ----
    float partial = 0.f;
    #pragma unroll 1
    for (int e = tid; e < 5376; e += NT) {
        int ln = e & 31;  int q  = e >> 5;
        int v  = q & 3;   int q2 = q >> 2;
        int nt = q2 % 3;  int tile = q2 / 3;
        int m = tile * 16 + (ln >> 2) + (v >> 1) * 8;
        int n = nt * 8 + (ln & 3) * 2 + (v & 1);
        if (m < 216 && n < 18) {
            int ox = m / 36; int oyz = m - ox * 36;
            int ch = n / 6;  int ow  = n - ch * 6;
            float h = Cred[e] + __ldg(cb + ch);
            h = fmaxf(h, 0.f);
            partial = fmaf(h, __ldg(lw + ch * 1296 + ox * 216 + oyz * 6 + ow),
                           partial);
        }
    }

    float* red = (float*)smem + 8192;
    red[tid] = partial;
    __syncthreads();
    if (tid < 128) red[tid] += red[tid + 128];
    __syncthreads();
    if (tid < 64)  red[tid] += red[tid + 64];
    __syncthreads();
    if (tid < 32) {
        float v = red[tid] + red[tid + 32];
        #pragma unroll
        for (int off = 16; off > 0; off >>= 1)
            v += __shfl_down_sync(0xffffffffu, v, off);
        if (tid == 0) {
            float z = v + __ldg(lb);
            out[b] = 1.f / (1.f + expf(-z));
        }
    }
}

extern "C" void kernel_launch(void* const* d_in, const int* in_sizes, int n_in,
                              void* d_out, int out_size)
{
    const float* x      = (const float*)d_in[0];
    const float* conv_w = (const float*)d_in[1];
    const float* conv_b = (const float*)d_in[2];
    const float* lin_w  = (const float*)d_in[3];
    const float* lin_b  = (const float*)d_in[4];
    float* out = (float*)d_out;

    cudaFuncSetAttribute(conv4d_mma_pair,
                         cudaFuncAttributeMaxDynamicSharedMemorySize, SMEM_BYTES);
    conv4d_mma_pair<<<512, NT, SMEM_BYTES>>>(x, conv_w, conv_b, lin_w, lin_b, out);
}

// round 13
// speedup vs baseline: 1.5101x; 1.4214x over previous
#include <cuda_runtime.h>
#include <cuda_fp16.h>
#include <cstdint>
#include <math.h>

#define SX 18
#define KS 13
#define W4 28561
#define W3 2197
#define W2 169
#define X3 5832
#define X2 324
#define XB 104976

// fp16 layouts (word = uint32_t = half2)
#define APITCHW 12                 // words per A row (24 halfs: k 0..17 + pad)
#define AROWS   656
#define AWORDSH (AROWS * APITCHW)             // 7872 words
#define BPITCHW 12                 // words per B n-row (24 halfs)
#define BWORDSH (13 * 24 * BPITCHW)           // 3744 words
#define TOTW    (AWORDSH + BWORDSH)           // 11616 words
#define SMEM_BYTES (TOTW * 4)                 // 46464 B
#define NT 256

__device__ __forceinline__ void mma_k16(float* c, uint32_t a0, uint32_t a1,
                                        uint32_t a2, uint32_t a3,
                                        uint32_t b0, uint32_t b1) {
    asm volatile(
        "mma.sync.aligned.m16n8k16.row.col.f32.f16.f16.f32 "
        "{%0,%1,%2,%3}, {%4,%5,%6,%7}, {%8,%9}, {%0,%1,%2,%3};"
        : "+f"(c[0]), "+f"(c[1]), "+f"(c[2]), "+f"(c[3])
        : "r"(a0), "r"(a1), "r"(a2), "r"(a3), "r"(b0), "r"(b1));
}
__device__ __forceinline__ void mma_k8(float* c, uint32_t a0, uint32_t a1,
                                       uint32_t b0) {
    asm volatile(
        "mma.sync.aligned.m16n8k8.row.col.f32.f16.f16.f32 "
        "{%0,%1,%2,%3}, {%4,%5}, {%6}, {%0,%1,%2,%3};"
        : "+f"(c[0]), "+f"(c[1]), "+f"(c[2]), "+f"(c[3])
        : "r"(a0), "r"(a1), "r"(b0));
}

__global__ __launch_bounds__(NT, 2)
void conv4d_mma_h(const float* __restrict__ x,  const float* __restrict__ cw,
                  const float* __restrict__ cb, const float* __restrict__ lw,
                  const float* __restrict__ lb, float* __restrict__ out)
{
    extern __shared__ uint32_t smem[];

    const int b   = blockIdx.x;
    const int tid = threadIdx.x;
    const int wid = tid >> 5;
    const int lid = tid & 31;
    const int g   = lid >> 2;
    const int tig = lid & 3;

    // warp = (m-quarter, kx-half)
    const int mq  = wid & 3;                        // tiles: 4/4/3/3
    const int kg  = wid >> 2;                       // kx: 7/6
    const int tbase  = (mq < 2) ? 4 * mq : 8 + 3 * (mq - 2);
    const int tcount = (mq < 2) ? 4 : 3;
    const int kxs = (kg == 0) ? 0 : 7;
    const int kxe = (kg == 0) ? 7 : 13;

    float c[4][3][4];
    #pragma unroll
    for (int t = 0; t < 4; ++t)
        #pragma unroll
        for (int n = 0; n < 3; ++n)
            #pragma unroll
            for (int v = 0; v < 4; ++v) c[t][n][v] = 0.f;

    // per-thread A staging offsets, packed: (src float2-idx << 13) | dst word-idx
    uint32_t pk[23];
    #pragma unroll
    for (int k = 0; k < 23; ++k) {
        int u = tid + k * NT;
        if (u < 5832) {
            int row = u / 9;   int j   = u - row * 9;
            int ix  = row / 36; int oyz = row - ix * 36;
            int oy  = oyz / 6;  int oz  = oyz - oy * 6;
            uint32_t srcU = (uint32_t)((ix * X3 + oy * X2 + oz * SX + 2 * j) >> 1);
            uint32_t dstW = (uint32_t)(row * APITCHW + j);
            pk[k] = (srcU << 13) | dstW;
        } else pk[k] = 0xFFFFFFFFu;
    }

    // zero everything once (A k-pads 18..23, pad rows, B holes & k-pads)
    for (int i = tid; i < TOTW; i += NT) smem[i] = 0u;

    const float* xb = x + (size_t)b * XB;
    const char*  xc = (const char*)xb;
    half* Bh = (half*)(smem + AWORDSH);

    #pragma unroll 1
    for (int i = 0; i < 169; ++i) {
        const int ky = i / 13, kz = i - 13 * (i / 13);
        const int d  = (ky * X2 + kz * SX) * 4;

        __syncthreads();   // previous compute's readers done

        // ---- stage A: LDG.64 -> half2 -> STS.32 ----
        #pragma unroll
        for (int k = 0; k < 23; ++k) {
            uint32_t p = pk[k];
            if (p != 0xFFFFFFFFu) {
                float2 v = *(const float2*)(xc + (size_t)(p >> 13) * 8 + d);
                __half2 h = __float22half2_rn(v);
                smem[p & 8191u] = *(const uint32_t*)&h;
            }
        }
        // ---- stage B (n-major): B[kx][n=ch*6+ow][k=ow+kw] ----
        for (int t = tid; t < 507; t += NT) {
            int kx = t / 39; int r = t - kx * 39;
            int ch = r / 13; int kw = r - ch * 13;
            half hw = __float2half_rn(cw[ch * W4 + kx * W3 + ky * W2 + kz * KS + kw]);
            half* dst = Bh + kx * 576 + ch * 6 * 24;
            #pragma unroll
            for (int ow = 0; ow < 6; ++ow)
                dst[ow * 24 + (ow + kw)] = hw;
        }

        __syncthreads();   // slab + B staged

        // ---- compute(i): own kx-half x own m-quarter ----
        #pragma unroll 1
        for (int kx = kxs; kx < kxe; ++kx) {
            // B frags: word base kx*288 + (nt*8+g)*12
            uint32_t bf0[3], bf1[3], bf2[3];
            {
                const uint32_t* Bw = smem + AWORDSH + kx * 288 + g * BPITCHW;
                #pragma unroll
                for (int nt = 0; nt < 3; ++nt) {
                    const uint32_t* p = Bw + nt * 8 * BPITCHW;
                    bf0[nt] = p[tig];          // k 2tig,2tig+1
                    bf1[nt] = p[tig + 4];      // k 8+2tig, 9+2tig
                    bf2[nt] = p[tig + 8];      // k 16+2tig, 17+2tig
                }
            }
            #pragma unroll
            for (int t = 0; t < 4; ++t) {
                if (t < tcount) {
                    const int rg = (tbase + t) * 16 + g + 36 * kx;
                    const uint32_t* Ar = smem + rg * APITCHW + tig;
                    uint32_t alo_g = Ar[0];                    // row g,  k 2tig..
                    uint32_t ahi_g = Ar[4];                    // row g,  k 8+2tig..
                    uint32_t ae_g  = Ar[8];                    // row g,  k 16+2tig..
                    uint32_t alo_h = Ar[8 * APITCHW];          // row g+8
                    uint32_t ahi_h = Ar[8 * APITCHW + 4];
                    uint32_t ae_h  = Ar[8 * APITCHW + 8];
                    #pragma unroll
                    for (int nt = 0; nt < 3; ++nt) {
                        mma_k16(c[t][nt], alo_g, alo_h, ahi_g, ahi_h,
                                bf0[nt], bf1[nt]);
                        mma_k8(c[t][nt], ae_g, ae_h, bf2[nt]);
                    }
                }
            }
        }
    }

    // ---- reduce C across the 2 kx-halves (tile-indexed, 2 phases) ----
    __syncthreads();
    float* Cred = (float*)smem;            // 5376 floats
    #pragma unroll 1
    for (int ph = 0; ph < 2; ++ph) {
        if (kg == ph) {
            #pragma unroll
            for (int t = 0; t < 4; ++t)
                if (t < tcount) {
                    int tile = tbase + t;
                    #pragma unroll
                    for (int nt = 0; nt < 3; ++nt)
                        #pragma unroll
                        for (int v = 0; v < 4; ++v) {
                            int idx = ((tile * 3 + nt) * 4 + v) * 32 + lid;
                            if (ph == 0) Cred[idx] = c[t][nt][v];
                            else         Cred[idx] += c[t][nt][v];
                        }
                }
        }
        __syncthreads();
    }

    // ---- epilogue: bias + ReLU + dot(lin_w) over 5376 C elements ----
    float partial = 0.f;
    #pragma unroll 1
    for (int e = tid; e < 5376; e += NT) {
        int ln = e & 31;  int q  = e >> 5;
        int v  = q & 3;   int q2 = q >> 2;
        int nt = q2 % 3;  int tile = q2 / 3;
        int m = tile * 16 + (ln >> 2) + (v >> 1) * 8;
        int n = nt * 8 + (ln & 3) * 2 + (v & 1);
        if (m < 216 && n < 18) {
            int ox = m / 36; int oyz = m - ox * 36;
            int ch = n / 6;  int ow  = n - ch * 6;
            float h = Cred[e] + __ldg(cb + ch);
            h = fmaxf(h, 0.f);
            partial = fmaf(h, __ldg(lw + ch * 1296 + ox * 216 + oyz * 6 + ow),
                           partial);
        }
    }

    float* red = (float*)smem + 8192;
    red[tid] = partial;
    __syncthreads();
    if (tid < 128) red[tid] += red[tid + 128];
    __syncthreads();
    if (tid < 64)  red[tid] += red[tid + 64];
    __syncthreads();
    if (tid < 32) {
        float v = red[tid] + red[tid + 32];
        #pragma unroll
        for (int off = 16; off > 0; off >>= 1)
            v += __shfl_down_sync(0xffffffffu, v, off);
        if (tid == 0) {
            float z = v + __ldg(lb);
            out[b] = 1.f / (1.f + expf(-z));
        }
    }
}

extern "C" void kernel_launch(void* const* d_in, const int* in_sizes, int n_in,
                              void* d_out, int out_size)
{
    const float* x      = (const float*)d_in[0];
    const float* conv_w = (const float*)d_in[1];
    const float* conv_b = (const float*)d_in[2];
    const float* lin_w  = (const float*)d_in[3];
    const float* lin_b  = (const float*)d_in[4];
    float* out = (float*)d_out;

    cudaFuncSetAttribute(conv4d_mma_h,
                         cudaFuncAttributeMaxDynamicSharedMemorySize, SMEM_BYTES);
    conv4d_mma_h<<<512, NT, SMEM_BYTES>>>(x, conv_w, conv_b, lin_w, lin_b, out);
}

// round 14
// speedup vs baseline: 1.6069x; 1.0641x over previous
#include <cuda_runtime.h>
#include <cuda_fp16.h>
#include <cstdint>
#include <math.h>

#define SX 18
#define KS 13
#define W4 28561
#define W3 2197
#define W2 169
#define X3 5832
#define X2 324
#define XB 104976
#define NB 512

#define APITCHW 12                       // u32 words per A row (24 halfs)
#define AROWS   656
#define AWORDSH (AROWS * APITCHW)        // 7872 words per A buffer
#define BWORDSH (13 * 24 * 12)           // 3744 words per B buffer
#define B0OFF   (2 * AWORDSH)            // 15744
#define TOTW    (2 * AWORDSH + 2 * BWORDSH)   // 23232 words
#define SMEM_BYTES (TOTW * 4)            // 92928 B -> 2 blocks/SM
#define NT 256

__device__ __half g_xh[(size_t)NB * XB];     // fp16 x (107.5 MB)
__device__ __half g_Bh[169 * 7488];          // fp16 Toeplitz B per (ky,kz)

__global__ void prep_x(const float* __restrict__ x) {
    size_t n4 = (size_t)NB * XB / 4;
    size_t stride = (size_t)gridDim.x * blockDim.x;
    for (size_t i = (size_t)blockIdx.x * blockDim.x + threadIdx.x; i < n4;
         i += stride) {
        float4 v = ((const float4*)x)[i];
        __half2 h0 = __floats2half2_rn(v.x, v.y);
        __half2 h1 = __floats2half2_rn(v.z, v.w);
        uint2 u; u.x = *(uint32_t*)&h0; u.y = *(uint32_t*)&h1;
        ((uint2*)g_xh)[i] = u;
    }
}

__global__ void prep_B(const float* __restrict__ cw) {
    int i = blockIdx.x;                      // 0..168
    int ky = i / 13, kz = i - 13 * (i / 13);
    uint32_t* z = (uint32_t*)(g_Bh + (size_t)i * 7488);
    for (int t = threadIdx.x; t < 3744; t += NT) z[t] = 0u;
    __syncthreads();
    for (int t = threadIdx.x; t < 507; t += NT) {
        int kx = t / 39; int r = t - kx * 39;
        int ch = r / 13; int kw = r - ch * 13;
        __half hw = __float2half_rn(cw[ch * W4 + kx * W3 + ky * W2 + kz * KS + kw]);
        __half* d = g_Bh + (size_t)i * 7488 + kx * 576 + ch * 6 * 24;
        #pragma unroll
        for (int ow = 0; ow < 6; ++ow)
            d[ow * 24 + ow + kw] = hw;       // B[n=ch*6+ow][k=ow+kw]
    }
}

__device__ __forceinline__ uint32_t smem_u32(const void* p) {
    uint32_t a; asm("{ .reg .u64 t; cvta.to.shared.u64 t, %1; cvt.u32.u64 %0, t; }"
                    : "=r"(a) : "l"(p));
    return a;
}
__device__ __forceinline__ void cp4(uint32_t dst, const void* src) {
    asm volatile("cp.async.ca.shared.global [%0], [%1], 4;"
                 :: "r"(dst), "l"(src) : "memory");
}
__device__ __forceinline__ void cp16(uint32_t dst, const void* src) {
    asm volatile("cp.async.cg.shared.global [%0], [%1], 16;"
                 :: "r"(dst), "l"(src) : "memory");
}
__device__ __forceinline__ void mma_k16(float* c, uint32_t a0, uint32_t a1,
                                        uint32_t a2, uint32_t a3,
                                        uint32_t b0, uint32_t b1) {
    asm volatile(
        "mma.sync.aligned.m16n8k16.row.col.f32.f16.f16.f32 "
        "{%0,%1,%2,%3}, {%4,%5,%6,%7}, {%8,%9}, {%0,%1,%2,%3};"
        : "+f"(c[0]), "+f"(c[1]), "+f"(c[2]), "+f"(c[3])
        : "r"(a0), "r"(a1), "r"(a2), "r"(a3), "r"(b0), "r"(b1));
}
__device__ __forceinline__ void mma_k8(float* c, uint32_t a0, uint32_t a1,
                                       uint32_t b0) {
    asm volatile(
        "mma.sync.aligned.m16n8k8.row.col.f32.f16.f16.f32 "
        "{%0,%1,%2,%3}, {%4,%5}, {%6}, {%0,%1,%2,%3};"
        : "+f"(c[0]), "+f"(c[1]), "+f"(c[2]), "+f"(c[3])
        : "r"(a0), "r"(a1), "r"(b0));
}

__global__ __launch_bounds__(NT, 2)
void conv4d_mma_h2(const float* __restrict__ cb, const float* __restrict__ lw,
                   const float* __restrict__ lb, float* __restrict__ out)
{
    extern __shared__ uint32_t smem[];
    const uint32_t sb = smem_u32(smem);

    const int b   = blockIdx.x;
    const int tid = threadIdx.x;
    const int wid = tid >> 5;
    const int lid = tid & 31;
    const int g   = lid >> 2;
    const int tig = lid & 3;

    const int mq  = wid & 3;                     // tiles: 4/4/3/3
    const int kg  = wid >> 2;                    // kx: 0..6 / 6..12 (kx6 split)
    const int tbase  = (mq < 2) ? 4 * mq : 8 + 3 * (mq - 2);
    const int tcount = (mq < 2) ? 4 : 3;
    const int kxs = (kg == 0) ? 0 : 6;
    const int kxe = (kg == 0) ? 6 : 12;

    float c[4][3][4];
    #pragma unroll
    for (int t = 0; t < 4; ++t)
        #pragma unroll
        for (int n = 0; n < 3; ++n)
            #pragma unroll
            for (int v = 0; v < 4; ++v) c[t][n][v] = 0.f;

    // A staging offsets: (src u32-idx in batch's g_xh slice << 13) | dst word
    uint32_t pk[23];
    #pragma unroll
    for (int k = 0; k < 23; ++k) {
        int u = tid + k * NT;
        if (u < 5832) {
            int row = u / 9;   int j   = u - row * 9;
            int ix  = row / 36; int oyz = row - ix * 36;
            int oy  = oyz / 6;  int oz  = oyz - oy * 6;
            uint32_t srcU = (uint32_t)((ix * X3 + oy * X2 + oz * SX) >> 1) + j;
            pk[k] = (srcU << 13) | (uint32_t)(row * APITCHW + j);
        } else pk[k] = 0xFFFFFFFFu;
    }

    // zero both A buffers once (k-pad words 9..11 per row, pad rows 648..655)
    for (int w = tid; w < 2 * AWORDSH; w += NT) smem[w] = 0u;
    __syncthreads();

    const char* xh = (const char*)(g_xh + (size_t)b * XB);
    const char* bh = (const char*)g_Bh;

    // ---- prologue: stage(0) into buffers 0 ----
    {
        #pragma unroll
        for (int k = 0; k < 23; ++k) {
            uint32_t p = pk[k];
            if (p != 0xFFFFFFFFu)
                cp4(sb + (p & 8191u) * 4u, xh + (size_t)(p >> 13) * 4);
        }
        #pragma unroll
        for (int k = 0; k < 4; ++k) {
            int u = tid + k * NT;
            if (u < 936) cp16(sb + B0OFF * 4 + u * 16, bh + u * 16);
        }
        asm volatile("cp.async.commit_group;" ::: "memory");
    }

    #pragma unroll 1
    for (int i = 0; i < 169; ++i) {
        __syncthreads();               // compute(i-1) readers done everywhere

        if (i < 168) {                 // stage(i+1) into buffer (i+1)&1
            const int ni = i + 1;
            const int ky = ni / 13, kz = ni - 13 * (ni / 13);
            const uint32_t dA = (uint32_t)((ky * X2 + kz * SX) >> 1);
            const uint32_t abufB = (uint32_t)((ni & 1) * AWORDSH) * 4u;
            #pragma unroll
            for (int k = 0; k < 23; ++k) {
                uint32_t p = pk[k];
                if (p != 0xFFFFFFFFu)
                    cp4(sb + abufB + (p & 8191u) * 4u,
                        xh + (size_t)((p >> 13) + dA) * 4);
            }
            const uint32_t bbufB = (uint32_t)(B0OFF + (ni & 1) * BWORDSH) * 4u;
            const char* bsrc = bh + (size_t)ni * 14976;
            #pragma unroll
            for (int k = 0; k < 4; ++k) {
                int u = tid + k * NT;
                if (u < 936) cp16(sb + bbufB + u * 16, bsrc + u * 16);
            }
            asm volatile("cp.async.commit_group;" ::: "memory");
            asm volatile("cp.async.wait_group 1;" ::: "memory");
        } else {
            asm volatile("cp.async.wait_group 0;" ::: "memory");
        }
        __syncthreads();               // all threads' stage(i) visible

        // ---- compute(i) ----
        const uint32_t* As = smem + (i & 1) * AWORDSH;
        const uint32_t* Bw0 = smem + B0OFF + (i & 1) * BWORDSH + g * APITCHW;
        #pragma unroll 1
        for (int kx = kxs; kx <= kxe; ++kx) {
            const bool do16 = !(kx == 6 && kg == 1);
            const bool do8  = !(kx == 6 && kg == 0);
            uint32_t bf0[3], bf1[3], bf2[3];
            {
                const uint32_t* Bw = Bw0 + kx * 288;
                #pragma unroll
                for (int nt = 0; nt < 3; ++nt) {
                    const uint32_t* p = Bw + nt * 8 * APITCHW;
                    bf0[nt] = p[tig];
                    bf1[nt] = p[tig + 4];
                    bf2[nt] = p[tig + 8];
                }
            }
            #pragma unroll
            for (int t = 0; t < 4; ++t) {
                if (t < tcount) {
                    const int rg = (tbase + t) * 16 + g + 36 * kx;
                    const uint32_t* Ar = As + rg * APITCHW + tig;
                    uint32_t alo_g = Ar[0];
                    uint32_t ahi_g = Ar[4];
                    uint32_t ae_g  = Ar[8];
                    uint32_t alo_h = Ar[8 * APITCHW];
                    uint32_t ahi_h = Ar[8 * APITCHW + 4];
                    uint32_t ae_h  = Ar[8 * APITCHW + 8];
                    #pragma unroll
                    for (int nt = 0; nt < 3; ++nt) {
                        if (do16) mma_k16(c[t][nt], alo_g, alo_h, ahi_g, ahi_h,
                                          bf0[nt], bf1[nt]);
                        if (do8)  mma_k8(c[t][nt], ae_g, ae_h, bf2[nt]);
                    }
                }
            }
        }
    }

    // ---- reduce C across kg (2 phases, tile-indexed) ----
    __syncthreads();
    float* Cred = (float*)smem;
    #pragma unroll 1
    for (int ph = 0; ph < 2; ++ph) {
        if (kg == ph) {
            #pragma unroll
            for (int t = 0; t < 4; ++t)
                if (t < tcount) {
                    int tile = tbase + t;
                    #pragma unroll
                    for (int nt = 0; nt < 3; ++nt)
                        #pragma unroll
                        for (int v = 0; v < 4; ++v) {
                            int idx = ((tile * 3 + nt) * 4 + v) * 32 + lid;
                            if (ph == 0) Cred[idx] = c[t][nt][v];
                            else         Cred[idx] += c[t][nt][v];
                        }
                }
        }
        __syncthreads();
    }

    // ---- epilogue: bias + ReLU + dot(lin_w) ----
    float partial = 0.f;
    #pragma unroll 1
    for (int e = tid; e < 5376; e += NT) {
        int ln = e & 31;  int q  = e >> 5;
        int v  = q & 3;   int q2 = q >> 2;
        int nt = q2 % 3;  int tile = q2 / 3;
        int m = tile * 16 + (ln >> 2) + (v >> 1) * 8;
        int n = nt * 8 + (ln & 3) * 2 + (v & 1);
        if (m < 216 && n < 18) {
            int ox = m / 36; int oyz = m - ox * 36;
            int ch = n / 6;  int ow  = n - ch * 6;
            float h = Cred[e] + __ldg(cb + ch);
            h = fmaxf(h, 0.f);
            partial = fmaf(h, __ldg(lw + ch * 1296 + ox * 216 + oyz * 6 + ow),
                           partial);
        }
    }

    float* red = (float*)smem + 8192;
    red[tid] = partial;
    __syncthreads();
    if (tid < 128) red[tid] += red[tid + 128];
    __syncthreads();
    if (tid < 64)  red[tid] += red[tid + 64];
    __syncthreads();
    if (tid < 32) {
        float v = red[tid] + red[tid + 32];
        #pragma unroll
        for (int off = 16; off > 0; off >>= 1)
            v += __shfl_down_sync(0xffffffffu, v, off);
        if (tid == 0) {
            float z = v + __ldg(lb);
            out[b] = 1.f / (1.f + expf(-z));
        }
    }
}

extern "C" void kernel_launch(void* const* d_in, const int* in_sizes, int n_in,
                              void* d_out, int out_size)
{
    const float* x      = (const float*)d_in[0];
    const float* conv_w = (const float*)d_in[1];
    const float* conv_b = (const float*)d_in[2];
    const float* lin_w  = (const float*)d_in[3];
    const float* lin_b  = (const float*)d_in[4];
    float* out = (float*)d_out;

    prep_x<<<4096, NT>>>(x);
    prep_B<<<169, NT>>>(conv_w);
    cudaFuncSetAttribute(conv4d_mma_h2,
                         cudaFuncAttributeMaxDynamicSharedMemorySize, SMEM_BYTES);
    conv4d_mma_h2<<<512, NT, SMEM_BYTES>>>(conv_b, lin_w, lin_b, out);
}